// round 1
// baseline (speedup 1.0000x reference)
#include <cuda_runtime.h>
#include <cstdint>

// Problem constants
#define Bc   128
#define Cc   64
#define Hc   32
#define Wc   32
#define NEDGE 6

#define PLANE   (Hc*Wc)                // 1024
#define IMGSZ   (Cc*PLANE)             // 65536
#define TOTSZ   (Bc*IMGSZ)             // 8388608
#define WSZ     (NEDGE*Cc*Cc*9)        // 2359296

// ---------------- device scratch (no allocs allowed) ----------------
__device__ float d_r0[TOTSZ];
__device__ float d_r1[TOTSZ];
__device__ float d_r2[TOTSZ];
__device__ float d_acc2[TOTSZ];
__device__ float d_acc3[TOTSZ];
__device__ float d_Wt[NEDGE*9*Cc*Cc];   // [l][s][ci][oc]
__device__ float d_ain[Cc];
__device__ float d_aout[Cc];

// ---------------- K0: cumulative channel scales ----------------
__global__ void scales_kernel(const float* __restrict__ a1,
                              const float* __restrict__ a2) {
    int c = threadIdx.x;
    if (c < Cc) {
        float s1 = 0.f, s2 = 0.f;
        #pragma unroll
        for (int i = 0; i < 8; i++) {
            if (c < 8*(i+1)) { s1 += a1[i]; s2 += a2[i]; }
        }
        d_ain[c]  = s1;
        d_aout[c] = s2;
    }
}

// ---------------- K1: weight transpose OIHW -> [l][s][ci][oc] ----------------
__global__ void transpose_w_kernel(const float* __restrict__ W) {
    int idx = blockIdx.x * 256 + threadIdx.x;
    if (idx >= NEDGE*9*Cc*Cc) return;
    int oc = idx & 63;
    int t  = idx >> 6;
    int ci = t & 63;  t >>= 6;
    int s  = t % 9;
    int l  = t / 9;
    d_Wt[idx] = W[(((l*Cc + oc)*Cc + ci)*9) + s];
}

// ---------------- K2: r0 = a_in * relu(x) ----------------
__global__ void prescale_kernel(const float* __restrict__ x) {
    int i = blockIdx.x * blockDim.x + threadIdx.x;     // float4 index
    const int NV = TOTSZ / 4;
    if (i >= NV) return;
    int c = (i >> 8) & 63;                             // 256 float4 per (b,c) plane
    float a = d_ain[c];
    float4 v = ((const float4*)x)[i];
    v.x = a * fmaxf(v.x, 0.f);
    v.y = a * fmaxf(v.y, 0.f);
    v.z = a * fmaxf(v.z, 0.f);
    v.w = a * fmaxf(v.w, 0.f);
    ((float4*)d_r0)[i] = v;
}

// ---------------- conv pass ----------------
// mode 0: out = conv + (addin ? addin : 0)            (plain accumulate)
// mode 1: out = a_in * relu(a_out * (conv + addin))   (produce next node's r)
// mode 2: out = a_out * (conv + addin)                (final node output)
struct EdgeSpec {
    int l;
    int mode;
    const float* addin;  // may be null
    float* out;
};

// block: (band 0..3, batch 0..127, edge), 256 threads
// thread: ocg = tid>>5 (8 oc), lane: r = lane>>2 (row in band), wg = lane&3 (8 cols)
__global__ __launch_bounds__(256, 2)
void conv_pass_kernel(const float* __restrict__ in,
                      EdgeSpec e0, EdgeSpec e1, EdgeSpec e2) {
    __shared__ float s_in[8][10][35];      // [ci_chunk][row(-1..+8)][col(-1..32) pad]
    __shared__ float s_wt[9][8][Cc];       // [s][ci_chunk][oc]

    EdgeSpec spec = (blockIdx.z == 0) ? e0 : (blockIdx.z == 1) ? e1 : e2;

    const int band = blockIdx.x;
    const int b    = blockIdx.y;
    const int tid  = threadIdx.x;
    const int ocg  = tid >> 5;
    const int lane = tid & 31;
    const int r    = lane >> 2;
    const int wg   = lane & 3;
    const int row0 = band * 8;

    float acc[8][8];   // [col j][oc o]
    #pragma unroll
    for (int j = 0; j < 8; j++)
        #pragma unroll
        for (int o = 0; o < 8; o++) acc[j][o] = 0.f;

    const float* wbase = d_Wt + (size_t)spec.l * 9 * Cc * Cc;
    const float* inb   = in + (size_t)b * IMGSZ;

    for (int chunk = 0; chunk < 8; chunk++) {
        __syncthreads();
        // ---- load input chunk: 8 ci x 10 rows x 34 cols ----
        for (int idx = tid; idx < 8*10*34; idx += 256) {
            int cc  = idx / 340;
            int rem = idx - cc * 340;
            int rr  = rem / 34;
            int cw  = rem - rr * 34;
            int gr  = row0 - 1 + rr;
            int w   = cw - 1;
            float v = 0.f;
            if ((unsigned)gr < 32u && (unsigned)w < 32u)
                v = inb[((chunk*8 + cc) * Hc + gr) * Wc + w];
            s_in[cc][rr][cw] = v;
        }
        // ---- load weight chunk: 9 s x 8 ci x 64 oc (coalesced) ----
        for (int idx = tid; idx < 9*8*64; idx += 256) {
            int s   = idx >> 9;
            int rem = idx & 511;
            int cc  = rem >> 6;
            int oc  = rem & 63;
            s_wt[s][cc][oc] = wbase[(s*Cc + chunk*8 + cc)*Cc + oc];
        }
        __syncthreads();

        // ---- compute ----
        #pragma unroll 1
        for (int cc = 0; cc < 8; cc++) {
            #pragma unroll
            for (int ky = 0; ky < 3; ky++) {
                float inv[10];
                #pragma unroll
                for (int j = 0; j < 10; j++)
                    inv[j] = s_in[cc][r + ky][wg*8 + j];
                #pragma unroll
                for (int kx = 0; kx < 3; kx++) {
                    const float4 w0 = *(const float4*)&s_wt[ky*3 + kx][cc][ocg*8];
                    const float4 w1 = *(const float4*)&s_wt[ky*3 + kx][cc][ocg*8 + 4];
                    #pragma unroll
                    for (int j = 0; j < 8; j++) {
                        float iv = inv[j + kx];
                        acc[j][0] += iv * w0.x;
                        acc[j][1] += iv * w0.y;
                        acc[j][2] += iv * w0.z;
                        acc[j][3] += iv * w0.w;
                        acc[j][4] += iv * w1.x;
                        acc[j][5] += iv * w1.y;
                        acc[j][6] += iv * w1.z;
                        acc[j][7] += iv * w1.w;
                    }
                }
            }
        }
    }

    // ---- epilogue ----
    const int row  = row0 + r;
    const int col0 = wg * 8;
    const int mode = spec.mode;
    #pragma unroll
    for (int o = 0; o < 8; o++) {
        int oc = ocg * 8 + o;
        float ai = d_ain[oc];
        float ao = d_aout[oc];
        size_t base = (((size_t)b * Cc + oc) * Hc + row) * Wc + col0;
        float v[8];
        #pragma unroll
        for (int j = 0; j < 8; j++) v[j] = acc[j][o];
        if (spec.addin) {
            float4 A0 = *(const float4*)(spec.addin + base);
            float4 A1 = *(const float4*)(spec.addin + base + 4);
            v[0] += A0.x; v[1] += A0.y; v[2] += A0.z; v[3] += A0.w;
            v[4] += A1.x; v[5] += A1.y; v[6] += A1.z; v[7] += A1.w;
        }
        if (mode == 1) {
            #pragma unroll
            for (int j = 0; j < 8; j++) v[j] = ai * fmaxf(ao * v[j], 0.f);
        } else if (mode == 2) {
            #pragma unroll
            for (int j = 0; j < 8; j++) v[j] *= ao;
        }
        *(float4*)(spec.out + base)     = make_float4(v[0], v[1], v[2], v[3]);
        *(float4*)(spec.out + base + 4) = make_float4(v[4], v[5], v[6], v[7]);
    }
}

// ---------------- launch ----------------
extern "C" void kernel_launch(void* const* d_in, const int* in_sizes, int n_in,
                              void* d_out, int out_size) {
    // Identify inputs robustly by size: inputs(8388608), alphas1(8), alphas2(8), W(2359296)
    const float* x  = nullptr;
    const float* a1 = nullptr;
    const float* a2 = nullptr;
    const float* W  = nullptr;
    for (int i = 0; i < n_in; i++) {
        if (in_sizes[i] == TOTSZ)      x = (const float*)d_in[i];
        else if (in_sizes[i] == WSZ)   W = (const float*)d_in[i];
        else if (in_sizes[i] == 8) {
            if (!a1) a1 = (const float*)d_in[i];
            else     a2 = (const float*)d_in[i];
        }
    }
    float* out = (float*)d_out;

    float *r0, *r1, *r2, *acc2, *acc3;
    cudaGetSymbolAddress((void**)&r0,   d_r0);
    cudaGetSymbolAddress((void**)&r1,   d_r1);
    cudaGetSymbolAddress((void**)&r2,   d_r2);
    cudaGetSymbolAddress((void**)&acc2, d_acc2);
    cudaGetSymbolAddress((void**)&acc3, d_acc3);

    scales_kernel<<<1, 64>>>(a1, a2);
    transpose_w_kernel<<<(NEDGE*9*Cc*Cc + 255)/256, 256>>>(W);
    prescale_kernel<<<(TOTSZ/4 + 255)/256, 256>>>(x);

    // Pass A: from r0 -> {r1 (W0), acc2 (W1), acc3 (W3)}
    EdgeSpec eA0{0, 1, nullptr, r1};
    EdgeSpec eA1{1, 0, nullptr, acc2};
    EdgeSpec eA2{3, 0, nullptr, acc3};
    conv_pass_kernel<<<dim3(4, Bc, 3), 256>>>(r0, eA0, eA1, eA2);

    // Pass B: from r1 -> {r2 (W2 + acc2), acc3 += W4}
    EdgeSpec eB0{2, 1, acc2, r2};
    EdgeSpec eB1{4, 0, acc3, acc3};
    conv_pass_kernel<<<dim3(4, Bc, 2), 256>>>(r1, eB0, eB1, eB1);

    // Pass C: out = a_out * (acc3 + conv(r2, W5))
    EdgeSpec eC0{5, 2, acc3, out};
    conv_pass_kernel<<<dim3(4, Bc, 1), 256>>>(r2, eC0, eC0, eC0);

    (void)out_size;
}